// round 2
// baseline (speedup 1.0000x reference)
#include <cuda_runtime.h>

// Multi-class hinge (Crammer-Singer) loss, summed over batch.
// outputs: [N, C] fp32, labels: [N] int32 (JAX demotes int64 -> int32),
// out: scalar fp32.
//
// sum_{i,j != y_i} max(outputs[i,j] - outputs[i,y_i] + 1, 0)
// The j == y_i term would contribute exactly 1.0, so we sum over all j and
// subtract 1.0 per row.

static constexpr int C_DIM = 4096;
static constexpr int THREADS = 256;            // 4096 / (4 * 256) = 4 float4 per thread

__global__ void zero_out_kernel(float* out) {
    if (threadIdx.x == 0) out[0] = 0.0f;
}

__global__ __launch_bounds__(THREADS) void hinge_loss_kernel(
    const float* __restrict__ outputs,
    const int* __restrict__ labels,
    float* __restrict__ out)
{
    const int row = blockIdx.x;
    const size_t row_off = (size_t)row * C_DIM;
    const float4* rowp = reinterpret_cast<const float4*>(outputs + row_off);

    const int lab = labels[row];
    const float g = outputs[row_off + (size_t)lab];
    const float t = 1.0f - g;   // margin = max(o + t, 0)

    const int tid = threadIdx.x;
    float s = 0.0f;
    #pragma unroll
    for (int i = 0; i < C_DIM / (4 * THREADS); i++) {
        float4 v = rowp[tid + i * THREADS];
        s += fmaxf(v.x + t, 0.0f);
        s += fmaxf(v.y + t, 0.0f);
        s += fmaxf(v.z + t, 0.0f);
        s += fmaxf(v.w + t, 0.0f);
    }

    // warp reduce
    #pragma unroll
    for (int o = 16; o > 0; o >>= 1)
        s += __shfl_xor_sync(0xFFFFFFFFu, s, o);

    __shared__ float ws[THREADS / 32];
    if ((tid & 31) == 0) ws[tid >> 5] = s;
    __syncthreads();

    if (tid == 0) {
        float v = ws[0];
        #pragma unroll
        for (int w = 1; w < THREADS / 32; w++) v += ws[w];
        // subtract the j == label contribution (exactly 1.0)
        atomicAdd(out, v - 1.0f);
    }
}

extern "C" void kernel_launch(void* const* d_in, const int* in_sizes, int n_in,
                              void* d_out, int out_size) {
    const float* outputs = (const float*)d_in[0];
    const int* labels = (const int*)d_in[1];
    float* out = (float*)d_out;

    const int N = in_sizes[1];          // 16384 labels

    zero_out_kernel<<<1, 32>>>(out);
    hinge_loss_kernel<<<N, THREADS>>>(outputs, labels, out);
}

// round 3
// speedup vs baseline: 1.0073x; 1.0073x over previous
#include <cuda_runtime.h>

// Multi-class hinge (Crammer-Singer) loss, summed over batch.
// outputs: [N, C] fp32, labels: [N] int32, out: scalar fp32.
//
// sum_{i,j != y_i} max(outputs[i,j] - outputs[i,y_i] + 1, 0)
// The j == y_i term contributes exactly 1.0, so we sum over all j and
// subtract 1.0 per row.
//
// Persistent grid-stride: 2048 CTAs x 8 rows each. Keeps the LDG pipeline
// full across row iterations (cross-row loads independent -> SW pipelining),
// and cuts the final atomics to 2048.

static constexpr int C_DIM   = 4096;
static constexpr int THREADS = 256;          // 4096 / (4*256) = 4 float4 per thread
static constexpr int GRID    = 2048;         // 16384 rows / 8 rows per CTA

__global__ void zero_out_kernel(float* out) {
    if (threadIdx.x == 0) out[0] = 0.0f;
}

__global__ __launch_bounds__(THREADS) void hinge_loss_kernel(
    const float* __restrict__ outputs,
    const int* __restrict__ labels,
    float* __restrict__ out,
    int N)
{
    const int tid = threadIdx.x;
    float acc = 0.0f;

    for (int row = blockIdx.x; row < N; row += gridDim.x) {
        const size_t row_off = (size_t)row * C_DIM;
        const float4* rowp = reinterpret_cast<const float4*>(outputs + row_off);

        const int lab = __ldg(labels + row);
        const float g = __ldg(outputs + row_off + (size_t)lab);
        const float t = 1.0f - g;               // margin = max(o + t, 0)

        // 4 independent 16B streaming loads, front-batched for MLP.
        float4 v0 = __ldcs(rowp + tid);
        float4 v1 = __ldcs(rowp + tid + THREADS);
        float4 v2 = __ldcs(rowp + tid + 2 * THREADS);
        float4 v3 = __ldcs(rowp + tid + 3 * THREADS);

        float s = 0.0f;
        s += fmaxf(v0.x + t, 0.0f); s += fmaxf(v0.y + t, 0.0f);
        s += fmaxf(v0.z + t, 0.0f); s += fmaxf(v0.w + t, 0.0f);
        s += fmaxf(v1.x + t, 0.0f); s += fmaxf(v1.y + t, 0.0f);
        s += fmaxf(v1.z + t, 0.0f); s += fmaxf(v1.w + t, 0.0f);
        s += fmaxf(v2.x + t, 0.0f); s += fmaxf(v2.y + t, 0.0f);
        s += fmaxf(v2.z + t, 0.0f); s += fmaxf(v2.w + t, 0.0f);
        s += fmaxf(v3.x + t, 0.0f); s += fmaxf(v3.y + t, 0.0f);
        s += fmaxf(v3.z + t, 0.0f); s += fmaxf(v3.w + t, 0.0f);

        acc += s;
        if (tid == 0) acc -= 1.0f;              // remove j == label term
    }

    // warp reduce
    #pragma unroll
    for (int o = 16; o > 0; o >>= 1)
        acc += __shfl_xor_sync(0xFFFFFFFFu, acc, o);

    __shared__ float ws[THREADS / 32];
    if ((tid & 31) == 0) ws[tid >> 5] = acc;
    __syncthreads();

    if (tid == 0) {
        float v = ws[0];
        #pragma unroll
        for (int w = 1; w < THREADS / 32; w++) v += ws[w];
        atomicAdd(out, v);
    }
}

extern "C" void kernel_launch(void* const* d_in, const int* in_sizes, int n_in,
                              void* d_out, int out_size) {
    const float* outputs = (const float*)d_in[0];
    const int* labels = (const int*)d_in[1];
    float* out = (float*)d_out;

    const int N = in_sizes[1];          // 16384 labels

    zero_out_kernel<<<1, 32>>>(out);
    hinge_loss_kernel<<<GRID, THREADS>>>(outputs, labels, out, N);
}